// round 2
// baseline (speedup 1.0000x reference)
#include <cuda_runtime.h>
#include <math.h>

// ---------------- constants ----------------
#define B_ 64
#define CIN 192
#define CC 384
#define NH 12
#define HD 32
#define NWIN 1024      // 64 images * 16 windows
#define NTOK 50        // 1 cls + 49 patch
#define ROWS (NWIN*NTOK)   // 51200
#define HIDN 1536
#define QKVN 1152
#define LNEPS 1e-5f

// ---------------- scratch (device globals, no allocation) ----------------
__device__ float g_tok[ROWS*CC];            // token residual stream [1024][50][384]
__device__ float g_xn[ROWS*CC];             // LN output
__device__ float g_qkv[ROWS*QKVN];          // qkv for local attention
__device__ float g_att[ROWS*CC];            // attention output (pre-proj)
__device__ float g_h[ROWS*HIDN];            // mlp hidden
__device__ float g_act_cls[B_*8*8*CIN];     // LN+GELU activations NHWC (cls stream)
__device__ float g_act_patch[B_*56*56*CIN]; // LN+GELU activations NHWC (patch stream)
__device__ float g_clsn[NWIN*CC];
__device__ float g_clsqkv[NWIN*QKVN];
__device__ float g_clsatt[NWIN*CC];

__device__ __forceinline__ float gelu_exact(float x) {
    return 0.5f * x * (1.0f + erff(x * 0.7071067811865475f));
}

// ---------------- LayerNorm2d + GELU (NCHW in -> NHWC out) ----------------
// one block (192 threads) per spatial position
__global__ void ln2d_gelu_kernel(const float* __restrict__ x, float* __restrict__ out,
                                 const float* __restrict__ g, const float* __restrict__ b,
                                 int HW) {
    int pos = blockIdx.x;              // b*HW + sp
    int bi = pos / HW, sp = pos % HW;
    int c = threadIdx.x;               // 0..191
    float v = x[((long)bi * CIN + c) * HW + sp];
    float s = v, s2 = v * v;
    __shared__ float red[2][6];
    #pragma unroll
    for (int o = 16; o > 0; o >>= 1) {
        s  += __shfl_down_sync(0xffffffffu, s,  o);
        s2 += __shfl_down_sync(0xffffffffu, s2, o);
    }
    int wid = c >> 5, lane = c & 31;
    if (lane == 0) { red[0][wid] = s; red[1][wid] = s2; }
    __syncthreads();
    if (wid == 0) {
        s  = (lane < 6) ? red[0][lane] : 0.f;
        s2 = (lane < 6) ? red[1][lane] : 0.f;
        #pragma unroll
        for (int o = 4; o > 0; o >>= 1) {
            s  += __shfl_down_sync(0xffffffffu, s,  o);
            s2 += __shfl_down_sync(0xffffffffu, s2, o);
        }
        if (lane == 0) { red[0][0] = s * (1.0f/CIN); red[1][0] = s2 * (1.0f/CIN); }
    }
    __syncthreads();
    float m = red[0][0];
    float var = red[1][0] - m * m;
    float y = (v - m) * rsqrtf(var + LNEPS) * g[c] + b[c];
    out[(long)pos * CIN + c] = gelu_exact(y);
}

// ---------------- depthwise-grouped stride-2 conv, writes into token layout ----------------
// grid: B*OH*OW blocks, 384 threads (one per out channel)
__global__ void dwconv_kernel(const float* __restrict__ act, const float* __restrict__ w,
                              const float* __restrict__ bias, int H, int W, int OH, int OW,
                              int is_cls) {
    int pos = blockIdx.x;
    int ow = pos % OW; int t = pos / OW;
    int oh = t % OH;   int bi = t / OH;
    int oc = threadIdx.x;
    int ic = oc >> 1;
    float acc = bias[oc];
    #pragma unroll
    for (int dy = 0; dy < 3; dy++) {
        int iy = 2 * oh - 1 + dy;
        if (iy < 0 || iy >= H) continue;
        #pragma unroll
        for (int dx = 0; dx < 3; dx++) {
            int ix = 2 * ow - 1 + dx;
            if (ix < 0 || ix >= W) continue;
            acc += w[(dy * 3 + dx) * CC + oc] * act[((long)(bi * H + iy) * W + ix) * CIN + ic];
        }
    }
    int win, tok;
    if (is_cls) { win = bi * 16 + oh * 4 + ow; tok = 0; }
    else        { win = bi * 16 + (oh / 7) * 4 + (ow / 7); tok = 1 + (oh % 7) * 7 + (ow % 7); }
    g_tok[((long)win * NTOK + tok) * CC + oc] = acc;
}

// ---------------- LayerNorm over 384 channels (strided rows) ----------------
__global__ void ln_kernel(const float* __restrict__ x, long rstride,
                          const float* __restrict__ g, const float* __restrict__ b,
                          float* __restrict__ out) {
    int row = blockIdx.x;
    const float* xr = x + (long)row * rstride;
    int c = threadIdx.x;              // 0..383
    float v = xr[c];
    float s = v, s2 = v * v;
    __shared__ float red[2][12];
    #pragma unroll
    for (int o = 16; o > 0; o >>= 1) {
        s  += __shfl_down_sync(0xffffffffu, s,  o);
        s2 += __shfl_down_sync(0xffffffffu, s2, o);
    }
    int wid = c >> 5, lane = c & 31;
    if (lane == 0) { red[0][wid] = s; red[1][wid] = s2; }
    __syncthreads();
    if (wid == 0) {
        s  = (lane < 12) ? red[0][lane] : 0.f;
        s2 = (lane < 12) ? red[1][lane] : 0.f;
        #pragma unroll
        for (int o = 8; o > 0; o >>= 1) {
            s  += __shfl_down_sync(0xffffffffu, s,  o);
            s2 += __shfl_down_sync(0xffffffffu, s2, o);
        }
        if (lane == 0) { red[0][0] = s * (1.0f/CC); red[1][0] = s2 * (1.0f/CC); }
    }
    __syncthreads();
    float m = red[0][0];
    float var = red[1][0] - m * m;
    out[(long)row * CC + c] = (v - m) * rsqrtf(var + LNEPS) * g[c] + b[c];
}

// ---------------- tiled fp32 GEMM: C = A[M,K] @ B[K,N] + bias ----------------
// mode 0: bias only;  mode 1: gelu(bias-added);  mode 2: residual add (Res, same ldc)
// C rows at stride ldc (allows direct scatter into token stream)
__global__ void __launch_bounds__(256)
sgemm_kernel(const float* __restrict__ A, const float* __restrict__ Bm,
             const float* __restrict__ bias,
             float* __restrict__ Cc, const float* __restrict__ Res,
             int M, int N, int K, long ldc, int mode) {
    __shared__ float As[16][65];
    __shared__ float Bs[16][65];
    int bx = blockIdx.x, by = blockIdx.y;
    int tid = threadIdx.x;
    int tx = tid & 15, ty = tid >> 4;
    float acc[4][4] = {};
    const float* Ab = A + (long)by * 64 * K;
    const float* Bb = Bm + bx * 64;
    for (int k0 = 0; k0 < K; k0 += 16) {
        #pragma unroll
        for (int i = 0; i < 4; i++) {
            int idx = tid + i * 256;
            int m = idx >> 4, kk = idx & 15;
            As[kk][m] = Ab[(long)m * K + k0 + kk];
        }
        #pragma unroll
        for (int i = 0; i < 4; i++) {
            int idx = tid + i * 256;
            int kk = idx >> 6, n = idx & 63;
            Bs[kk][n] = Bb[(long)(k0 + kk) * N + n];
        }
        __syncthreads();
        #pragma unroll
        for (int kk = 0; kk < 16; kk++) {
            float a[4], bb[4];
            #pragma unroll
            for (int i = 0; i < 4; i++) a[i] = As[kk][ty * 4 + i];
            #pragma unroll
            for (int j = 0; j < 4; j++) bb[j] = Bs[kk][tx * 4 + j];
            #pragma unroll
            for (int i = 0; i < 4; i++)
                #pragma unroll
                for (int j = 0; j < 4; j++)
                    acc[i][j] = fmaf(a[i], bb[j], acc[i][j]);
        }
        __syncthreads();
    }
    #pragma unroll
    for (int i = 0; i < 4; i++) {
        int m = by * 64 + ty * 4 + i;
        #pragma unroll
        for (int j = 0; j < 4; j++) {
            int n = bx * 64 + tx * 4 + j;
            float v = acc[i][j] + bias[n];
            if (mode == 1) v = gelu_exact(v);
            else if (mode == 2) v += Res[(long)m * ldc + n];
            Cc[(long)m * ldc + n] = v;
        }
    }
}

// ---------------- local attention (50 tokens, rel-pos bias on patch-patch) ----------------
// one block (256 threads) per (window, head)
__global__ void attn_local_kernel(const float* __restrict__ qkv,
                                  const float* __restrict__ rp,   // [12][169] for this block
                                  float* __restrict__ out) {
    int w = blockIdx.x / NH, h = blockIdx.x % NH;
    __shared__ float q[50][33], k[50][33], v[50][33];
    __shared__ float p[8][50];
    int tid = threadIdx.x;
    for (int i = tid; i < 50 * 32; i += 256) {
        int t = i >> 5, d = i & 31;
        long base = ((long)(w * NTOK + t)) * QKVN + h * HD + d;
        q[t][d] = qkv[base];
        k[t][d] = qkv[base + CC];
        v[t][d] = qkv[base + 2 * CC];
    }
    __syncthreads();
    int wid = tid >> 5, lane = tid & 31;
    const float scale = 0.17677669529663687f;  // 1/sqrt(32)
    const float* rph = rp + h * 169;
    for (int qi = wid; qi < 50; qi += 8) {
        int k0 = lane, k1 = lane + 32;
        float s0, s1 = -1e30f;
        {
            float acc = 0.f;
            #pragma unroll
            for (int d = 0; d < 32; d++) acc += q[qi][d] * k[k0][d];
            s0 = acc * scale;
            if (qi > 0 && k0 > 0) {
                int qr = (qi - 1) / 7, qc = (qi - 1) % 7;
                int kr = (k0 - 1) / 7, kc = (k0 - 1) % 7;
                s0 += rph[(qr - kr + 6) * 13 + (qc - kc + 6)];
            }
        }
        if (k1 < 50) {
            float acc = 0.f;
            #pragma unroll
            for (int d = 0; d < 32; d++) acc += q[qi][d] * k[k1][d];
            s1 = acc * scale;
            if (qi > 0) {
                int qr = (qi - 1) / 7, qc = (qi - 1) % 7;
                int kr = (k1 - 1) / 7, kc = (k1 - 1) % 7;
                s1 += rph[(qr - kr + 6) * 13 + (qc - kc + 6)];
            }
        }
        float m = fmaxf(s0, s1);
        #pragma unroll
        for (int o = 16; o > 0; o >>= 1) m = fmaxf(m, __shfl_xor_sync(0xffffffffu, m, o));
        float e0 = expf(s0 - m);
        float e1 = (k1 < 50) ? expf(s1 - m) : 0.f;
        float sum = e0 + e1;
        #pragma unroll
        for (int o = 16; o > 0; o >>= 1) sum += __shfl_xor_sync(0xffffffffu, sum, o);
        p[wid][k0] = e0;
        if (k1 < 50) p[wid][k1] = e1;
        __syncwarp();
        float inv = 1.f / sum;
        float acc = 0.f;
        #pragma unroll 10
        for (int kk = 0; kk < 50; kk++) acc += p[wid][kk] * v[kk][lane];
        out[((long)(w * NTOK + qi)) * CC + h * HD + lane] = acc * inv;
        __syncwarp();
    }
}

// ---------------- regional attention (16 cls tokens per image, no bias) ----------------
// one block (128 threads) per (image, head)
__global__ void attn_reg_kernel(const float* __restrict__ qkv, float* __restrict__ out) {
    int bi = blockIdx.x / NH, h = blockIdx.x % NH;
    __shared__ float q[16][33], k[16][33], v[16][33];
    __shared__ float p[4][16];
    int tid = threadIdx.x;
    for (int i = tid; i < 16 * 32; i += 128) {
        int t = i >> 5, d = i & 31;
        long base = ((long)(bi * 16 + t)) * QKVN + h * HD + d;
        q[t][d] = qkv[base];
        k[t][d] = qkv[base + CC];
        v[t][d] = qkv[base + 2 * CC];
    }
    __syncthreads();
    int wid = tid >> 5, lane = tid & 31;
    const float scale = 0.17677669529663687f;
    for (int qi = wid; qi < 16; qi += 4) {
        float s0 = -1e30f;
        if (lane < 16) {
            float acc = 0.f;
            #pragma unroll
            for (int d = 0; d < 32; d++) acc += q[qi][d] * k[lane][d];
            s0 = acc * scale;
        }
        float m = s0;
        #pragma unroll
        for (int o = 16; o > 0; o >>= 1) m = fmaxf(m, __shfl_xor_sync(0xffffffffu, m, o));
        float e0 = (lane < 16) ? expf(s0 - m) : 0.f;
        float sum = e0;
        #pragma unroll
        for (int o = 16; o > 0; o >>= 1) sum += __shfl_xor_sync(0xffffffffu, sum, o);
        if (lane < 16) p[wid][lane] = e0;
        __syncwarp();
        float inv = 1.f / sum;
        float acc = 0.f;
        #pragma unroll
        for (int kk = 0; kk < 16; kk++) acc += p[wid][kk] * v[kk][lane];
        out[((long)(bi * 16 + qi)) * CC + h * HD + lane] = acc * inv;
        __syncwarp();
    }
}

// ---------------- fold tokens back to (cls_out, patch_out) output ----------------
__global__ void write_out_kernel(float* __restrict__ out) {
    const int CLS = B_ * CC * 16;              // 393216
    const int TOT = CLS + B_ * CC * 784;       // 19660800
    int idx = blockIdx.x * blockDim.x + threadIdx.x;
    if (idx >= TOT) return;
    if (idx < CLS) {
        int w = idx & 3; int t = idx >> 2;
        int h = t & 3;   t >>= 2;
        int c = t % CC;  int bi = t / CC;
        out[idx] = g_tok[((long)(bi * 16 + h * 4 + w) * NTOK) * CC + c];
    } else {
        int i2 = idx - CLS;
        int ow = i2 % 28; int t = i2 / 28;
        int oh = t % 28;  t /= 28;
        int c = t % CC;   int bi = t / CC;
        int win = bi * 16 + (oh / 7) * 4 + (ow / 7);
        int tok = 1 + (oh % 7) * 7 + (ow % 7);
        out[idx] = g_tok[((long)win * NTOK + tok) * CC + c];
    }
}

// ---------------- host orchestration ----------------
extern "C" void kernel_launch(void* const* d_in, const int* in_sizes, int n_in,
                              void* d_out, int out_size) {
    const float* cls   = (const float*)d_in[0];
    const float* patch = (const float*)d_in[1];
    const float* plg   = (const float*)d_in[2];
    const float* plb   = (const float*)d_in[3];
    const float* pcw   = (const float*)d_in[4];
    const float* pcb   = (const float*)d_in[5];
    const float* n0g   = (const float*)d_in[6];
    const float* n0b   = (const float*)d_in[7];
    const float* n1g   = (const float*)d_in[8];
    const float* n1b   = (const float*)d_in[9];
    const float* n2g   = (const float*)d_in[10];
    const float* n2b   = (const float*)d_in[11];
    const float* qkvw  = (const float*)d_in[12];
    const float* qkvb  = (const float*)d_in[13];
    const float* apw   = (const float*)d_in[14];
    const float* apb   = (const float*)d_in[15];
    const float* rp    = (const float*)d_in[16];
    const float* fc1w  = (const float*)d_in[17];
    const float* fc1b  = (const float*)d_in[18];
    const float* fc2w  = (const float*)d_in[19];
    const float* fc2b  = (const float*)d_in[20];

    float *p_tok, *p_xn, *p_qkv, *p_att, *p_h, *p_ac, *p_ap, *p_cn, *p_cq, *p_ca;
    cudaGetSymbolAddress((void**)&p_tok, g_tok);
    cudaGetSymbolAddress((void**)&p_xn,  g_xn);
    cudaGetSymbolAddress((void**)&p_qkv, g_qkv);
    cudaGetSymbolAddress((void**)&p_att, g_att);
    cudaGetSymbolAddress((void**)&p_h,   g_h);
    cudaGetSymbolAddress((void**)&p_ac,  g_act_cls);
    cudaGetSymbolAddress((void**)&p_ap,  g_act_patch);
    cudaGetSymbolAddress((void**)&p_cn,  g_clsn);
    cudaGetSymbolAddress((void**)&p_cq,  g_clsqkv);
    cudaGetSymbolAddress((void**)&p_ca,  g_clsatt);

    // ---- projection stage ----
    ln2d_gelu_kernel<<<B_ * 64,   CIN>>>(cls,   p_ac, plg, plb, 64);
    ln2d_gelu_kernel<<<B_ * 3136, CIN>>>(patch, p_ap, plg, plb, 3136);
    dwconv_kernel<<<B_ * 16,  CC>>>(p_ac, pcw, pcb, 8, 8, 4, 4, 1);
    dwconv_kernel<<<B_ * 784, CC>>>(p_ap, pcw, pcb, 56, 56, 28, 28, 0);

    // ---- 2 R2L blocks ----
    for (int i = 0; i < 2; i++) {
        const float* qw = qkvw + (long)i * CC * QKVN;
        const float* qb = qkvb + (long)i * QKVN;
        const float* aw = apw  + (long)i * CC * CC;
        const float* ab = apb  + (long)i * CC;

        // regional (cls) attention across windows
        ln_kernel<<<NWIN, CC>>>(p_tok, (long)NTOK * CC, n0g + i * CC, n0b + i * CC, p_cn);
        { dim3 g(QKVN / 64, NWIN / 64);
          sgemm_kernel<<<g, 256>>>(p_cn, qw, qb, p_cq, nullptr, NWIN, QKVN, CC, QKVN, 0); }
        attn_reg_kernel<<<B_ * NH, 128>>>(p_cq, p_ca);
        { dim3 g(CC / 64, NWIN / 64);
          sgemm_kernel<<<g, 256>>>(p_ca, aw, ab, p_tok, p_tok, NWIN, CC, CC, (long)NTOK * CC, 2); }

        // local attention within windows
        ln_kernel<<<ROWS, CC>>>(p_tok, CC, n1g + i * CC, n1b + i * CC, p_xn);
        { dim3 g(QKVN / 64, ROWS / 64);
          sgemm_kernel<<<g, 256>>>(p_xn, qw, qb, p_qkv, nullptr, ROWS, QKVN, CC, QKVN, 0); }
        attn_local_kernel<<<NWIN * NH, 256>>>(p_qkv, rp + (long)i * NH * 169, p_att);
        { dim3 g(CC / 64, ROWS / 64);
          sgemm_kernel<<<g, 256>>>(p_att, aw, ab, p_tok, p_tok, ROWS, CC, CC, CC, 2); }

        // MLP
        ln_kernel<<<ROWS, CC>>>(p_tok, CC, n2g + i * CC, n2b + i * CC, p_xn);
        { dim3 g(HIDN / 64, ROWS / 64);
          sgemm_kernel<<<g, 256>>>(p_xn, fc1w + (long)i * CC * HIDN, fc1b + i * HIDN,
                                   p_h, nullptr, ROWS, HIDN, CC, HIDN, 1); }
        { dim3 g(CC / 64, ROWS / 64);
          sgemm_kernel<<<g, 256>>>(p_h, fc2w + (long)i * HIDN * CC, fc2b + i * CC,
                                   p_tok, p_tok, ROWS, CC, HIDN, CC, 2); }
    }

    // ---- fold to output ----
    const int TOT = B_ * CC * 16 + B_ * CC * 784;
    write_out_kernel<<<(TOT + 255) / 256, 256>>>((float*)d_out);
}

// round 9
// speedup vs baseline: 2.8561x; 2.8561x over previous
#include <cuda_runtime.h>
#include <cuda_bf16.h>
#include <math.h>

// ---------------- constants ----------------
#define B_ 64
#define CIN 192
#define CC 384
#define NH 12
#define HD 32
#define NWIN 1024
#define NTOK 50
#define ROWS (NWIN*NTOK)   // 51200
#define HIDN 1536
#define QKVN 1152
#define LNEPS 1e-5f

typedef __nv_bfloat16 bf16;
typedef __nv_bfloat162 bf162;

// ---------------- scratch (device globals) ----------------
__device__ float g_tok[ROWS*CC];              // fp32 residual stream
__device__ float g_act_cls[B_*8*8*CIN];
__device__ float g_act_patch[B_*56*56*CIN];
// split-bf16 activation planes (hi + lo)
__device__ bf16  g_xn_h[ROWS*CC],   g_xn_l[ROWS*CC];
__device__ bf16  g_qkv_h[ROWS*QKVN],g_qkv_l[ROWS*QKVN];
__device__ bf16  g_att_h[ROWS*CC],  g_att_l[ROWS*CC];
__device__ bf16  g_h_h[ROWS*HIDN],  g_h_l[ROWS*HIDN];
__device__ bf16  g_cn_h[NWIN*CC],   g_cn_l[NWIN*CC];
__device__ bf16  g_cq_h[NWIN*QKVN], g_cq_l[NWIN*QKVN];
__device__ bf16  g_ca_h[NWIN*CC],   g_ca_l[NWIN*CC];
// split-bf16 weights
__device__ bf16  g_qkvw_h[2*CC*QKVN], g_qkvw_l[2*CC*QKVN];
__device__ bf16  g_apw_h[2*CC*CC],    g_apw_l[2*CC*CC];
__device__ bf16  g_fc1w_h[2*CC*HIDN], g_fc1w_l[2*CC*HIDN];
__device__ bf16  g_fc2w_h[2*HIDN*CC], g_fc2w_l[2*HIDN*CC];

__device__ __forceinline__ float gelu_exact(float x) {
    return 0.5f * x * (1.0f + erff(x * 0.7071067811865475f));
}
__device__ __forceinline__ void split2(float v, bf16& h, bf16& l) {
    h = __float2bfloat16(v);
    l = __float2bfloat16(v - __bfloat162float(h));
}

// ---------------- fp32 -> split bf16 ----------------
__global__ void f2bf_split_kernel(const float* __restrict__ in,
                                  bf16* __restrict__ oh, bf16* __restrict__ ol, int n) {
    int i = blockIdx.x * blockDim.x + threadIdx.x;
    int stride = gridDim.x * blockDim.x;
    for (; i < n; i += stride) { bf16 h, l; split2(in[i], h, l); oh[i] = h; ol[i] = l; }
}

// ---------------- LayerNorm2d + GELU (NCHW in -> NHWC out, fp32) ----------------
__global__ void ln2d_gelu_kernel(const float* __restrict__ x, float* __restrict__ out,
                                 const float* __restrict__ g, const float* __restrict__ b,
                                 int HW) {
    int pos = blockIdx.x;
    int bi = pos / HW, sp = pos % HW;
    int c = threadIdx.x;
    float v = x[((long)bi * CIN + c) * HW + sp];
    float s = v, s2 = v * v;
    __shared__ float red[2][6];
    #pragma unroll
    for (int o = 16; o > 0; o >>= 1) {
        s  += __shfl_down_sync(0xffffffffu, s,  o);
        s2 += __shfl_down_sync(0xffffffffu, s2, o);
    }
    int wid = c >> 5, lane = c & 31;
    if (lane == 0) { red[0][wid] = s; red[1][wid] = s2; }
    __syncthreads();
    if (wid == 0) {
        s  = (lane < 6) ? red[0][lane] : 0.f;
        s2 = (lane < 6) ? red[1][lane] : 0.f;
        #pragma unroll
        for (int o = 4; o > 0; o >>= 1) {
            s  += __shfl_down_sync(0xffffffffu, s,  o);
            s2 += __shfl_down_sync(0xffffffffu, s2, o);
        }
        if (lane == 0) { red[0][0] = s * (1.0f/CIN); red[1][0] = s2 * (1.0f/CIN); }
    }
    __syncthreads();
    float m = red[0][0];
    float var = red[1][0] - m * m;
    float y = (v - m) * rsqrtf(var + LNEPS) * g[c] + b[c];
    out[(long)pos * CIN + c] = gelu_exact(y);
}

// ---------------- depthwise-grouped stride-2 conv -> token layout (fp32) ----------------
__global__ void dwconv_kernel(const float* __restrict__ act, const float* __restrict__ w,
                              const float* __restrict__ bias, int H, int W, int OH, int OW,
                              int is_cls) {
    int pos = blockIdx.x;
    int ow = pos % OW; int t = pos / OW;
    int oh = t % OH;   int bi = t / OH;
    int oc = threadIdx.x;
    int ic = oc >> 1;
    float acc = bias[oc];
    #pragma unroll
    for (int dy = 0; dy < 3; dy++) {
        int iy = 2 * oh - 1 + dy;
        if (iy < 0 || iy >= H) continue;
        #pragma unroll
        for (int dx = 0; dx < 3; dx++) {
            int ix = 2 * ow - 1 + dx;
            if (ix < 0 || ix >= W) continue;
            acc += w[(dy * 3 + dx) * CC + oc] * act[((long)(bi * H + iy) * W + ix) * CIN + ic];
        }
    }
    int win, tok;
    if (is_cls) { win = bi * 16 + oh * 4 + ow; tok = 0; }
    else        { win = bi * 16 + (oh / 7) * 4 + (ow / 7); tok = 1 + (oh % 7) * 7 + (ow % 7); }
    g_tok[((long)win * NTOK + tok) * CC + oc] = acc;
}

// ---------------- LayerNorm over 384 ch (fp32 strided in -> split bf16 out) ----------------
__global__ void ln_kernel(const float* __restrict__ x, long rstride,
                          const float* __restrict__ g, const float* __restrict__ b,
                          bf16* __restrict__ oh, bf16* __restrict__ ol) {
    int row = blockIdx.x;
    const float* xr = x + (long)row * rstride;
    int c = threadIdx.x;
    float v = xr[c];
    float s = v, s2 = v * v;
    __shared__ float red[2][12];
    #pragma unroll
    for (int o = 16; o > 0; o >>= 1) {
        s  += __shfl_down_sync(0xffffffffu, s,  o);
        s2 += __shfl_down_sync(0xffffffffu, s2, o);
    }
    int wid = c >> 5, lane = c & 31;
    if (lane == 0) { red[0][wid] = s; red[1][wid] = s2; }
    __syncthreads();
    if (wid == 0) {
        s  = (lane < 12) ? red[0][lane] : 0.f;
        s2 = (lane < 12) ? red[1][lane] : 0.f;
        #pragma unroll
        for (int o = 8; o > 0; o >>= 1) {
            s  += __shfl_down_sync(0xffffffffu, s,  o);
            s2 += __shfl_down_sync(0xffffffffu, s2, o);
        }
        if (lane == 0) { red[0][0] = s * (1.0f/CC); red[1][0] = s2 * (1.0f/CC); }
    }
    __syncthreads();
    float m = red[0][0];
    float var = red[1][0] - m * m;
    float y = (v - m) * rsqrtf(var + LNEPS) * g[c] + b[c];
    bf16 h, l; split2(y, h, l);
    oh[(long)row * CC + c] = h;
    ol[(long)row * CC + c] = l;
}

// ---------------- split-bf16 HMMA GEMM ----------------
// C = (Ah+Al)[M,K] @ (Bh+Bl)[K,N] + bias, via hi*hi + hi*lo + lo*hi
// mode 0: split bf16 out (Ch,Cl); mode 1: gelu -> split out; mode 2: fp32 Ch += Res
#define BM 128
#define BN 128
#define BK 32
#define ASTRIDE 80           // 64B row + 16B pad
#define BSTRIDE 272          // 256B row + 16B pad
#define APLANE (BM*ASTRIDE)  // 10240
#define BPLANE (BK*BSTRIDE)  // 8704
#define STAGEB (2*APLANE+2*BPLANE)  // 37888
#define GEMM_SMEM (2*STAGEB)        // 75776

__device__ __forceinline__ void cpasync16(unsigned s, const void* g) {
    asm volatile("cp.async.cg.shared.global [%0], [%1], 16;" :: "r"(s), "l"(g));
}
__device__ __forceinline__ void ldsm4(unsigned* r, unsigned a) {
    asm volatile("ldmatrix.sync.aligned.m8n8.x4.shared.b16 {%0,%1,%2,%3}, [%4];"
        : "=r"(r[0]), "=r"(r[1]), "=r"(r[2]), "=r"(r[3]) : "r"(a));
}
__device__ __forceinline__ void ldsm4t(unsigned* r, unsigned a) {
    asm volatile("ldmatrix.sync.aligned.m8n8.x4.trans.shared.b16 {%0,%1,%2,%3}, [%4];"
        : "=r"(r[0]), "=r"(r[1]), "=r"(r[2]), "=r"(r[3]) : "r"(a));
}
__device__ __forceinline__ void mma16816(float* c, const unsigned* a, const unsigned* b) {
    asm volatile("mma.sync.aligned.m16n8k16.row.col.f32.bf16.bf16.f32 "
        "{%0,%1,%2,%3}, {%4,%5,%6,%7}, {%8,%9}, {%0,%1,%2,%3};"
        : "+f"(c[0]), "+f"(c[1]), "+f"(c[2]), "+f"(c[3])
        : "r"(a[0]), "r"(a[1]), "r"(a[2]), "r"(a[3]), "r"(b[0]), "r"(b[1]));
}

__global__ void __launch_bounds__(256, 2)
hgemm_kernel(const bf16* __restrict__ Ah, const bf16* __restrict__ Al,
             const bf16* __restrict__ Bh, const bf16* __restrict__ Bl,
             const float* __restrict__ bias,
             void* __restrict__ Ch, bf16* __restrict__ Cl,
             const float* __restrict__ Res,
             int M, int N, int K, long ldc, int mode) {
    extern __shared__ char dsm[];
    unsigned sbase;
    { unsigned long long t; asm("cvta.to.shared.u64 %0, %1;" : "=l"(t) : "l"(dsm)); sbase = (unsigned)t; }
    int tid = threadIdx.x;
    int wid = tid >> 5, lane = tid & 31;
    int warp_m = wid >> 2, warp_n = wid & 3;
    int bm = blockIdx.y * BM, bn = blockIdx.x * BN;
    const bf16* Agh = Ah + (long)bm * K;
    const bf16* Agl = Al + (long)bm * K;
    const bf16* Bgh = Bh + bn;
    const bf16* Bgl = Bl + bn;

    float acc[4][4][4] = {};

    auto load_tile = [&](int k0, int buf) {
        unsigned base = sbase + buf * STAGEB;
        #pragma unroll
        for (int p = 0; p < 2; p++) {           // A hi plane: 512 16B chunks
            int id = tid + p * 256;
            int r = id >> 2, c = id & 3;
            cpasync16(base + r * ASTRIDE + c * 16, Agh + (long)r * K + k0 + c * 8);
        }
        #pragma unroll
        for (int p = 0; p < 2; p++) {           // A lo plane
            int id = tid + p * 256;
            int r = id >> 2, c = id & 3;
            cpasync16(base + APLANE + r * ASTRIDE + c * 16, Agl + (long)r * K + k0 + c * 8);
        }
        #pragma unroll
        for (int p = 0; p < 2; p++) {           // B hi plane: 512 chunks
            int id = tid + p * 256;
            int r = id >> 4, c = id & 15;
            cpasync16(base + 2 * APLANE + r * BSTRIDE + c * 16, Bgh + (long)(k0 + r) * N + c * 8);
        }
        #pragma unroll
        for (int p = 0; p < 2; p++) {           // B lo plane
            int id = tid + p * 256;
            int r = id >> 4, c = id & 15;
            cpasync16(base + 2 * APLANE + BPLANE + r * BSTRIDE + c * 16, Bgl + (long)(k0 + r) * N + c * 8);
        }
        asm volatile("cp.async.commit_group;");
    };

    int nit = K / BK;
    load_tile(0, 0);
    for (int it = 0; it < nit; it++) {
        if (it + 1 < nit) {
            load_tile((it + 1) * BK, (it + 1) & 1);
            asm volatile("cp.async.wait_group 1;");
        } else {
            asm volatile("cp.async.wait_group 0;");
        }
        __syncthreads();
        unsigned base = sbase + (it & 1) * STAGEB;
        unsigned a_hi = base, a_lo = base + APLANE;
        unsigned b_hi = base + 2 * APLANE, b_lo = b_hi + BPLANE;
        #pragma unroll
        for (int kk = 0; kk < 2; kk++) {        // two k16 slices per BK=32
            unsigned arow = (unsigned)((warp_m * 64 + (lane & 15)) * ASTRIDE + kk * 32 + (lane >> 4) * 16);
            unsigned brow = (unsigned)((kk * 16 + (lane & 15)) * BSTRIDE + (warp_n * 32 + (lane >> 4) * 8) * 2);
            // B fragments (hi and lo)
            unsigned bfh[4][2], bfl[4][2];
            #pragma unroll
            for (int gb = 0; gb < 2; gb++) {
                unsigned r4[4];
                ldsm4t(r4, b_hi + brow + gb * 32);
                bfh[gb * 2 + 0][0] = r4[0]; bfh[gb * 2 + 0][1] = r4[1];
                bfh[gb * 2 + 1][0] = r4[2]; bfh[gb * 2 + 1][1] = r4[3];
                ldsm4t(r4, b_lo + brow + gb * 32);
                bfl[gb * 2 + 0][0] = r4[0]; bfl[gb * 2 + 0][1] = r4[1];
                bfl[gb * 2 + 1][0] = r4[2]; bfl[gb * 2 + 1][1] = r4[3];
            }
            // phase 1: A_hi x (B_hi + B_lo)
            unsigned af[4][4];
            #pragma unroll
            for (int mt = 0; mt < 4; mt++) ldsm4(af[mt], a_hi + arow + mt * 16 * ASTRIDE);
            #pragma unroll
            for (int mt = 0; mt < 4; mt++)
                #pragma unroll
                for (int nt = 0; nt < 4; nt++) {
                    mma16816(acc[mt][nt], af[mt], bfh[nt]);
                    mma16816(acc[mt][nt], af[mt], bfl[nt]);
                }
            // phase 2: A_lo x B_hi
            #pragma unroll
            for (int mt = 0; mt < 4; mt++) ldsm4(af[mt], a_lo + arow + mt * 16 * ASTRIDE);
            #pragma unroll
            for (int mt = 0; mt < 4; mt++)
                #pragma unroll
                for (int nt = 0; nt < 4; nt++)
                    mma16816(acc[mt][nt], af[mt], bfh[nt]);
        }
        __syncthreads();
    }

    // epilogue
    int m0 = bm + warp_m * 64, n0 = bn + warp_n * 32;
    #pragma unroll
    for (int mt = 0; mt < 4; mt++) {
        #pragma unroll
        for (int nt = 0; nt < 4; nt++) {
            int m = m0 + mt * 16 + (lane >> 2);
            int n = n0 + nt * 8 + (lane & 3) * 2;
            float b0v = bias[n], b1v = bias[n + 1];
            float* c = acc[mt][nt];
            if (mode == 2) {
                float* out = (float*)Ch;
                {
                    long o = (long)m * ldc + n;
                    float2 r = *(const float2*)(Res + o);
                    float2 w; w.x = c[0] + b0v + r.x; w.y = c[1] + b1v + r.y;
                    *(float2*)(out + o) = w;
                }
                {
                    long o = (long)(m + 8) * ldc + n;
                    float2 r = *(const float2*)(Res + o);
                    float2 w; w.x = c[2] + b0v + r.x; w.y = c[3] + b1v + r.y;
                    *(float2*)(out + o) = w;
                }
            } else {
                bf16* oh = (bf16*)Ch;
                float v0 = c[0] + b0v, v1 = c[1] + b1v;
                float v2 = c[2] + b0v, v3 = c[3] + b1v;
                if (mode == 1) { v0 = gelu_exact(v0); v1 = gelu_exact(v1);
                                 v2 = gelu_exact(v2); v3 = gelu_exact(v3); }
                bf162 h0, l0, h1, l1;
                split2(v0, h0.x, l0.x); split2(v1, h0.y, l0.y);
                split2(v2, h1.x, l1.x); split2(v3, h1.y, l1.y);
                long o0 = (long)m * ldc + n, o1 = (long)(m + 8) * ldc + n;
                *(bf162*)(oh + o0) = h0; *(bf162*)(Cl + o0) = l0;
                *(bf162*)(oh + o1) = h1; *(bf162*)(Cl + o1) = l1;
            }
        }
    }
}

// ---------------- local attention (split qkv in, split out) ----------------
__global__ void attn_local_kernel(const bf16* __restrict__ qh, const bf16* __restrict__ ql,
                                  const float* __restrict__ rp,
                                  bf16* __restrict__ oh, bf16* __restrict__ ol) {
    int w = blockIdx.x / NH, h = blockIdx.x % NH;
    __shared__ float q[50][33], k[50][33], v[50][33];
    __shared__ float p[8][50];
    int tid = threadIdx.x;
    for (int i = tid; i < 50 * 32; i += 256) {
        int t = i >> 5, d = i & 31;
        long base = ((long)(w * NTOK + t)) * QKVN + h * HD + d;
        q[t][d] = __bfloat162float(qh[base])          + __bfloat162float(ql[base]);
        k[t][d] = __bfloat162float(qh[base + CC])     + __bfloat162float(ql[base + CC]);
        v[t][d] = __bfloat162float(qh[base + 2 * CC]) + __bfloat162float(ql[base + 2 * CC]);
    }
    __syncthreads();
    int wid = tid >> 5, lane = tid & 31;
    const float scale = 0.17677669529663687f;
    const float* rph = rp + h * 169;
    for (int qi = wid; qi < 50; qi += 8) {
        int k0 = lane, k1 = lane + 32;
        float s0, s1 = -1e30f;
        {
            float acc = 0.f;
            #pragma unroll
            for (int d = 0; d < 32; d++) acc += q[qi][d] * k[k0][d];
            s0 = acc * scale;
            if (qi > 0 && k0 > 0) {
                int qr = (qi - 1) / 7, qc = (qi - 1) % 7;
                int kr = (k0 - 1) / 7, kc = (k0 - 1) % 7;
                s0 += rph[(qr - kr + 6) * 13 + (qc - kc + 6)];
            }
        }
        if (k1 < 50) {
            float acc = 0.f;
            #pragma unroll
            for (int d = 0; d < 32; d++) acc += q[qi][d] * k[k1][d];
            s1 = acc * scale;
            if (qi > 0) {
                int qr = (qi - 1) / 7, qc = (qi - 1) % 7;
                int kr = (k1 - 1) / 7, kc = (k1 - 1) % 7;
                s1 += rph[(qr - kr + 6) * 13 + (qc - kc + 6)];
            }
        }
        float m = fmaxf(s0, s1);
        #pragma unroll
        for (int o = 16; o > 0; o >>= 1) m = fmaxf(m, __shfl_xor_sync(0xffffffffu, m, o));
        float e0 = expf(s0 - m);
        float e1 = (k1 < 50) ? expf(s1 - m) : 0.f;
        float sum = e0 + e1;
        #pragma unroll
        for (int o = 16; o > 0; o >>= 1) sum += __shfl_xor_sync(0xffffffffu, sum, o);
        p[wid][k0] = e0;
        if (k1 < 50) p[wid][k1] = e1;
        __syncwarp();
        float inv = 1.f / sum;
        float acc = 0.f;
        #pragma unroll 10
        for (int kk = 0; kk < 50; kk++) acc += p[wid][kk] * v[kk][lane];
        long o = ((long)(w * NTOK + qi)) * CC + h * HD + lane;
        bf16 hh, ll; split2(acc * inv, hh, ll);
        oh[o] = hh; ol[o] = ll;
        __syncwarp();
    }
}

// ---------------- regional attention (split qkv in, split out) ----------------
__global__ void attn_reg_kernel(const bf16* __restrict__ qh, const bf16* __restrict__ ql,
                                bf16* __restrict__ oh, bf16* __restrict__ ol) {
    int bi = blockIdx.x / NH, h = blockIdx.x % NH;
    __shared__ float q[16][33], k[16][33], v[16][33];
    __shared__ float p[4][16];
    int tid = threadIdx.x;
    for (int i = tid; i < 16 * 32; i += 128) {
        int t = i >> 5, d = i & 31;
        long base = ((long)(bi * 16 + t)) * QKVN + h * HD + d;
        q[t][d] = __bfloat162float(qh[base])          + __bfloat162float(ql[base]);
        k[t][d] = __bfloat162float(qh[base + CC])     + __bfloat162float(ql[base + CC]);
        v[t][d] = __bfloat162float(qh[base + 2 * CC]) + __bfloat162float(ql[base + 2 * CC]);
    }
    __syncthreads();
    int wid = tid >> 5, lane = tid & 31;
    const float scale = 0.17677669529663687f;
    for (int qi = wid; qi < 16; qi += 4) {
        float s0 = -1e30f;
        if (lane < 16) {
            float acc = 0.f;
            #pragma unroll
            for (int d = 0; d < 32; d++) acc += q[qi][d] * k[lane][d];
            s0 = acc * scale;
        }
        float m = s0;
        #pragma unroll
        for (int o = 16; o > 0; o >>= 1) m = fmaxf(m, __shfl_xor_sync(0xffffffffu, m, o));
        float e0 = (lane < 16) ? expf(s0 - m) : 0.f;
        float sum = e0;
        #pragma unroll
        for (int o = 16; o > 0; o >>= 1) sum += __shfl_xor_sync(0xffffffffu, sum, o);
        if (lane < 16) p[wid][lane] = e0;
        __syncwarp();
        float inv = 1.f / sum;
        float acc = 0.f;
        #pragma unroll
        for (int kk = 0; kk < 16; kk++) acc += p[wid][kk] * v[kk][lane];
        long o = ((long)(bi * 16 + qi)) * CC + h * HD + lane;
        bf16 hh, ll; split2(acc * inv, hh, ll);
        oh[o] = hh; ol[o] = ll;
        __syncwarp();
    }
}

// ---------------- fold tokens back to (cls_out, patch_out) ----------------
__global__ void write_out_kernel(float* __restrict__ out) {
    const int CLS = B_ * CC * 16;
    const int TOT = CLS + B_ * CC * 784;
    int idx = blockIdx.x * blockDim.x + threadIdx.x;
    if (idx >= TOT) return;
    if (idx < CLS) {
        int w = idx & 3; int t = idx >> 2;
        int h = t & 3;   t >>= 2;
        int c = t % CC;  int bi = t / CC;
        out[idx] = g_tok[((long)(bi * 16 + h * 4 + w) * NTOK) * CC + c];
    } else {
        int i2 = idx - CLS;
        int ow = i2 % 28; int t = i2 / 28;
        int oh = t % 28;  t /= 28;
        int c = t % CC;   int bi = t / CC;
        int win = bi * 16 + (oh / 7) * 4 + (ow / 7);
        int tok = 1 + (oh % 7) * 7 + (ow % 7);
        out[idx] = g_tok[((long)win * NTOK + tok) * CC + c];
    }
}

// ---------------- host orchestration ----------------
extern "C" void kernel_launch(void* const* d_in, const int* in_sizes, int n_in,
                              void* d_out, int out_size) {
    const float* cls   = (const float*)d_in[0];
    const float* patch = (const float*)d_in[1];
    const float* plg   = (const float*)d_in[2];
    const float* plb   = (const float*)d_in[3];
    const float* pcw   = (const float*)d_in[4];
    const float* pcb   = (const float*)d_in[5];
    const float* n0g   = (const float*)d_in[6];
    const float* n0b   = (const float*)d_in[7];
    const float* n1g   = (const float*)d_in[8];
    const float* n1b   = (const float*)d_in[9];
    const float* n2g   = (const float*)d_in[10];
    const float* n2b   = (const float*)d_in[11];
    const float* qkvw  = (const float*)d_in[12];
    const float* qkvb  = (const float*)d_in[13];
    const float* apw   = (const float*)d_in[14];
    const float* apb   = (const float*)d_in[15];
    const float* rp    = (const float*)d_in[16];
    const float* fc1w  = (const float*)d_in[17];
    const float* fc1b  = (const float*)d_in[18];
    const float* fc2w  = (const float*)d_in[19];
    const float* fc2b  = (const float*)d_in[20];

    float *p_tok, *p_ac, *p_ap;
    bf16 *xn_h, *xn_l, *qk_h, *qk_l, *at_h, *at_l, *hh_h, *hh_l;
    bf16 *cn_h, *cn_l, *cq_h, *cq_l, *ca_h, *ca_l;
    bf16 *wq_h, *wq_l, *wa_h, *wa_l, *w1_h, *w1_l, *w2_h, *w2_l;
    cudaGetSymbolAddress((void**)&p_tok, g_tok);
    cudaGetSymbolAddress((void**)&p_ac,  g_act_cls);
    cudaGetSymbolAddress((void**)&p_ap,  g_act_patch);
    cudaGetSymbolAddress((void**)&xn_h, g_xn_h);  cudaGetSymbolAddress((void**)&xn_l, g_xn_l);
    cudaGetSymbolAddress((void**)&qk_h, g_qkv_h); cudaGetSymbolAddress((void**)&qk_l, g_qkv_l);
    cudaGetSymbolAddress((void**)&at_h, g_att_h); cudaGetSymbolAddress((void**)&at_l, g_att_l);
    cudaGetSymbolAddress((void**)&hh_h, g_h_h);   cudaGetSymbolAddress((void**)&hh_l, g_h_l);
    cudaGetSymbolAddress((void**)&cn_h, g_cn_h);  cudaGetSymbolAddress((void**)&cn_l, g_cn_l);
    cudaGetSymbolAddress((void**)&cq_h, g_cq_h);  cudaGetSymbolAddress((void**)&cq_l, g_cq_l);
    cudaGetSymbolAddress((void**)&ca_h, g_ca_h);  cudaGetSymbolAddress((void**)&ca_l, g_ca_l);
    cudaGetSymbolAddress((void**)&wq_h, g_qkvw_h); cudaGetSymbolAddress((void**)&wq_l, g_qkvw_l);
    cudaGetSymbolAddress((void**)&wa_h, g_apw_h);  cudaGetSymbolAddress((void**)&wa_l, g_apw_l);
    cudaGetSymbolAddress((void**)&w1_h, g_fc1w_h); cudaGetSymbolAddress((void**)&w1_l, g_fc1w_l);
    cudaGetSymbolAddress((void**)&w2_h, g_fc2w_h); cudaGetSymbolAddress((void**)&w2_l, g_fc2w_l);

    cudaFuncSetAttribute(hgemm_kernel, cudaFuncAttributeMaxDynamicSharedMemorySize, GEMM_SMEM);

    // ---- weight conversion (split bf16) ----
    f2bf_split_kernel<<<432, 256>>>(qkvw, wq_h, wq_l, 2 * CC * QKVN);
    f2bf_split_kernel<<<144, 256>>>(apw,  wa_h, wa_l, 2 * CC * CC);
    f2bf_split_kernel<<<576, 256>>>(fc1w, w1_h, w1_l, 2 * CC * HIDN);
    f2bf_split_kernel<<<576, 256>>>(fc2w, w2_h, w2_l, 2 * HIDN * CC);

    // ---- projection stage ----
    ln2d_gelu_kernel<<<B_ * 64,   CIN>>>(cls,   p_ac, plg, plb, 64);
    ln2d_gelu_kernel<<<B_ * 3136, CIN>>>(patch, p_ap, plg, plb, 3136);
    dwconv_kernel<<<B_ * 16,  CC>>>(p_ac, pcw, pcb, 8, 8, 4, 4, 1);
    dwconv_kernel<<<B_ * 784, CC>>>(p_ap, pcw, pcb, 56, 56, 28, 28, 0);

    // ---- 2 R2L blocks ----
    for (int i = 0; i < 2; i++) {
        const bf16 *qwh = wq_h + (long)i * CC * QKVN, *qwl = wq_l + (long)i * CC * QKVN;
        const bf16 *awh = wa_h + (long)i * CC * CC,   *awl = wa_l + (long)i * CC * CC;
        const float* qb = qkvb + (long)i * QKVN;
        const float* ab = apb + (long)i * CC;

        // regional (cls) attention
        ln_kernel<<<NWIN, CC>>>(p_tok, (long)NTOK * CC, n0g + i * CC, n0b + i * CC, cn_h, cn_l);
        { dim3 g(QKVN / BN, NWIN / BM);
          hgemm_kernel<<<g, 256, GEMM_SMEM>>>(cn_h, cn_l, qwh, qwl, qb, cq_h, cq_l, nullptr,
                                              NWIN, QKVN, CC, QKVN, 0); }
        attn_reg_kernel<<<B_ * NH, 128>>>(cq_h, cq_l, ca_h, ca_l);
        { dim3 g(CC / BN, NWIN / BM);
          hgemm_kernel<<<g, 256, GEMM_SMEM>>>(ca_h, ca_l, awh, awl, ab, p_tok, nullptr, p_tok,
                                              NWIN, CC, CC, (long)NTOK * CC, 2); }

        // local attention
        ln_kernel<<<ROWS, CC>>>(p_tok, CC, n1g + i * CC, n1b + i * CC, xn_h, xn_l);
        { dim3 g(QKVN / BN, ROWS / BM);
          hgemm_kernel<<<g, 256, GEMM_SMEM>>>(xn_h, xn_l, qwh, qwl, qb, qk_h, qk_l, nullptr,
                                              ROWS, QKVN, CC, QKVN, 0); }
        attn_local_kernel<<<NWIN * NH, 256>>>(qk_h, qk_l, rp + (long)i * NH * 169, at_h, at_l);
        { dim3 g(CC / BN, ROWS / BM);
          hgemm_kernel<<<g, 256, GEMM_SMEM>>>(at_h, at_l, awh, awl, ab, p_tok, nullptr, p_tok,
                                              ROWS, CC, CC, CC, 2); }

        // MLP
        ln_kernel<<<ROWS, CC>>>(p_tok, CC, n2g + i * CC, n2b + i * CC, xn_h, xn_l);
        { dim3 g(HIDN / BN, ROWS / BM);
          hgemm_kernel<<<g, 256, GEMM_SMEM>>>(xn_h, xn_l,
                                              w1_h + (long)i * CC * HIDN, w1_l + (long)i * CC * HIDN,
                                              fc1b + i * HIDN, hh_h, hh_l, nullptr,
                                              ROWS, HIDN, CC, HIDN, 1); }
        { dim3 g(CC / BN, ROWS / BM);
          hgemm_kernel<<<g, 256, GEMM_SMEM>>>(hh_h, hh_l,
                                              w2_h + (long)i * HIDN * CC, w2_l + (long)i * HIDN * CC,
                                              fc2b + i * CC, p_tok, nullptr, p_tok,
                                              ROWS, CC, HIDN, CC, 2); }
    }

    // ---- fold to output ----
    const int TOT = B_ * CC * 16 + B_ * CC * 784;
    write_out_kernel<<<(TOT + 255) / 256, 256>>>((float*)d_out);
}